// round 1
// baseline (speedup 1.0000x reference)
#include <cuda_runtime.h>
#include <cuda_bf16.h>
#include <math.h>

// Problem constants (fixed by the reference)
#define NN 50000
#define NE 600000
#define NG 64
#define DH 128
#define DCAT 1664          // 13 * 128
#define DLAT 64

// ---------------- scratch (device globals; no allocation allowed) ----------
__device__ int   g_deg[NN];
__device__ int   g_off[NN + 1];
__device__ int   g_cur[NN];
__device__ int   g_csr[NE];
__device__ float g_delta[1];
__device__ float g_h0[(size_t)NN * DH];
__device__ float g_h1[(size_t)NN * DH];
__device__ float g_feat[(size_t)NN * DCAT];
__device__ float g_pool[NG * DH];

// ---------------- graph prep ----------------------------------------------
__global__ void hist_kernel(const int* __restrict__ ei) {
    int e = blockIdx.x * blockDim.x + threadIdx.x;
    int stride = gridDim.x * blockDim.x;
    for (; e < NE; e += stride) {
        int dst = ei[NE + e];
        atomicAdd(&g_deg[dst], 1);
    }
}

// single-block chunked exclusive scan of g_deg -> g_off (g_off[NN] = total)
__global__ void scan_kernel() {
    __shared__ int sh[1024];
    int t = threadIdx.x;
    int carry = 0;
    for (int base = 0; base < NN; base += 1024) {
        int v = (base + t < NN) ? g_deg[base + t] : 0;
        sh[t] = v;
        __syncthreads();
        #pragma unroll
        for (int s = 1; s < 1024; s <<= 1) {
            int add = (t >= s) ? sh[t - s] : 0;
            __syncthreads();
            sh[t] += add;
            __syncthreads();
        }
        if (base + t < NN) g_off[base + t] = carry + sh[t] - v;
        carry += sh[1023];
        __syncthreads();
    }
    if (t == 0) g_off[NN] = carry;
}

__global__ void scatter_kernel(const int* __restrict__ ei) {
    int e = blockIdx.x * blockDim.x + threadIdx.x;
    int stride = gridDim.x * blockDim.x;
    for (; e < NE; e += stride) {
        int src = ei[e];
        int dst = ei[NE + e];
        int pos = g_off[dst] + atomicAdd(&g_cur[dst], 1);
        g_csr[pos] = src;
    }
}

__global__ void delta_kernel() {
    int i = blockIdx.x * blockDim.x + threadIdx.x;
    int stride = gridDim.x * blockDim.x;
    float s = 0.f;
    for (; i < NN; i += stride) s += logf((float)g_deg[i] + 1.f);
    #pragma unroll
    for (int o = 16; o > 0; o >>= 1) s += __shfl_down_sync(0xffffffffu, s, o);
    __shared__ float sh[32];
    int lane = threadIdx.x & 31, wid = threadIdx.x >> 5;
    if (lane == 0) sh[wid] = s;
    __syncthreads();
    if (wid == 0) {
        float v = (lane < (int)(blockDim.x >> 5)) ? sh[lane] : 0.f;
        #pragma unroll
        for (int o = 16; o > 0; o >>= 1) v += __shfl_down_sync(0xffffffffu, v, o);
        if (lane == 0) atomicAdd(&g_delta[0], v);
    }
}

// ---------------- per-node aggregation + feature build ---------------------
// 1 block per node, 128 threads (thread = feature channel).
__global__ __launch_bounds__(128) void agg_feat_kernel(
        const float* __restrict__ h, float* __restrict__ feat) {
    int n = blockIdx.x;
    int t = threadIdx.x;
    int beg = g_off[n], end = g_off[n + 1];
    int d = end - beg;
    float hv = h[(size_t)n * DH + t];
    float s = 0.f, ss = 0.f;
    float mx = __int_as_float(0xff800000);  // -inf
    float mn = __int_as_float(0x7f800000);  // +inf
    __shared__ int ssrc[128];
    for (int base = beg; base < end; base += 128) {
        int cnt = min(128, end - base);
        if (t < cnt) ssrc[t] = g_csr[base + t];
        __syncthreads();
        #pragma unroll 4
        for (int i = 0; i < cnt; i++) {
            float m = h[(size_t)ssrc[i] * DH + t];
            s += m; ss += m * m;
            mx = fmaxf(mx, m); mn = fminf(mn, m);
        }
        __syncthreads();
    }
    float cntf = fmaxf((float)d, 1.f);
    float mean = s / cntf;
    float var  = fmaxf(ss / cntf - mean * mean, 0.f);
    float stdv = sqrtf(var + 1e-5f);
    if (d == 0) { mx = 0.f; mn = 0.f; }
    float delta = g_delta[0] * (1.f / (float)NN);
    float logd = logf((float)d + 1.f);
    float amp = logd / delta;
    float att = delta / fmaxf(logd, 1e-5f);
    size_t b = (size_t)n * DCAT;
    feat[b +    0 + t] = hv;
    feat[b +  128 + t] = mean;
    feat[b +  256 + t] = mx;
    feat[b +  384 + t] = mn;
    feat[b +  512 + t] = stdv;
    feat[b +  640 + t] = mean * amp;
    feat[b +  768 + t] = mx * amp;
    feat[b +  896 + t] = mn * amp;
    feat[b + 1024 + t] = stdv * amp;
    feat[b + 1152 + t] = mean * att;
    feat[b + 1280 + t] = mx * att;
    feat[b + 1408 + t] = mn * att;
    feat[b + 1536 + t] = stdv * att;
}

// ---------------- SGEMM: out[M,128] = relu(A[M,1664] @ W[1664,128] + b) ----
#define BM 128
#define BN 128
#define BK 32
#define APAD 4

__global__ __launch_bounds__(256, 2) void gemm_relu_kernel(
        const float* __restrict__ A, const float* __restrict__ W,
        const float* __restrict__ bias, float* __restrict__ out, int M) {
    const int K = DCAT;
    __shared__ float As[BK][BM + APAD];
    __shared__ float Bs[BK][BN];
    int tid = threadIdx.x;
    int row0 = blockIdx.x * BM;
    int tx = tid & 15;   // 0..15 -> output cols tx*8..+8
    int ty = tid >> 4;   // 0..15 -> output rows ty*8..+8
    float acc[8][8];
    #pragma unroll
    for (int i = 0; i < 8; i++)
        #pragma unroll
        for (int j = 0; j < 8; j++) acc[i][j] = 0.f;

    for (int k0 = 0; k0 < K; k0 += BK) {
        // load A tile 128x32 (transposed into As[k][m])
        #pragma unroll
        for (int l = 0; l < 4; l++) {
            int idx = tid + l * 256;       // float4 index (1024 total)
            int r  = idx >> 3;             // row in tile 0..127
            int c4 = idx & 7;              // float4 col 0..7
            int row = row0 + r;
            float4 v = make_float4(0.f, 0.f, 0.f, 0.f);
            if (row < M)
                v = *(const float4*)&A[(size_t)row * K + k0 + c4 * 4];
            As[c4 * 4 + 0][r] = v.x;
            As[c4 * 4 + 1][r] = v.y;
            As[c4 * 4 + 2][r] = v.z;
            As[c4 * 4 + 3][r] = v.w;
        }
        // load B tile 32x128
        #pragma unroll
        for (int l = 0; l < 4; l++) {
            int idx = tid + l * 256;
            int r  = idx >> 5;             // 0..31
            int c4 = idx & 31;             // 0..31
            *(float4*)&Bs[r][c4 * 4] =
                *(const float4*)&W[(size_t)(k0 + r) * BN + c4 * 4];
        }
        __syncthreads();
        #pragma unroll
        for (int k = 0; k < BK; k++) {
            float a[8], bb[8];
            *(float4*)(a)     = *(const float4*)&As[k][ty * 8];
            *(float4*)(a + 4) = *(const float4*)&As[k][ty * 8 + 4];
            *(float4*)(bb)     = *(const float4*)&Bs[k][tx * 8];
            *(float4*)(bb + 4) = *(const float4*)&Bs[k][tx * 8 + 4];
            #pragma unroll
            for (int i = 0; i < 8; i++)
                #pragma unroll
                for (int j = 0; j < 8; j++)
                    acc[i][j] += a[i] * bb[j];
        }
        __syncthreads();
    }
    // epilogue: bias + relu, vectorized stores
    float bfr[8];
    *(float4*)(bfr)     = *(const float4*)&bias[tx * 8];
    *(float4*)(bfr + 4) = *(const float4*)&bias[tx * 8 + 4];
    #pragma unroll
    for (int i = 0; i < 8; i++) {
        int row = row0 + ty * 8 + i;
        if (row < M) {
            float4 v0, v1;
            v0.x = fmaxf(acc[i][0] + bfr[0], 0.f);
            v0.y = fmaxf(acc[i][1] + bfr[1], 0.f);
            v0.z = fmaxf(acc[i][2] + bfr[2], 0.f);
            v0.w = fmaxf(acc[i][3] + bfr[3], 0.f);
            v1.x = fmaxf(acc[i][4] + bfr[4], 0.f);
            v1.y = fmaxf(acc[i][5] + bfr[5], 0.f);
            v1.z = fmaxf(acc[i][6] + bfr[6], 0.f);
            v1.w = fmaxf(acc[i][7] + bfr[7], 0.f);
            *(float4*)&out[(size_t)row * BN + tx * 8]     = v0;
            *(float4*)&out[(size_t)row * BN + tx * 8 + 4] = v1;
        }
    }
}

// ---------------- pooling (sorted batch -> run-length + few atomics) -------
#define POOL_NB 256
__global__ __launch_bounds__(128) void pool_kernel(
        const float* __restrict__ h, const int* __restrict__ batch) {
    int n0 = blockIdx.x * POOL_NB;
    int t = threadIdx.x;  // feature
    int nend = min(n0 + POOL_NB, NN);
    int cnt = nend - n0;
    __shared__ int sb[POOL_NB];
    for (int i = t; i < cnt; i += 128) sb[i] = batch[n0 + i];
    __syncthreads();
    float acc = 0.f;
    int cur = sb[0];
    for (int i = 0; i < cnt; i++) {
        int b = sb[i];
        if (b != cur) {
            atomicAdd(&g_pool[cur * DH + t], acc);
            acc = 0.f; cur = b;
        }
        acc += h[(size_t)(n0 + i) * DH + t];
    }
    atomicAdd(&g_pool[cur * DH + t], acc);
}

// ---------------- batchnorm (over graphs) + final FC ------------------------
__global__ __launch_bounds__(128) void bnfc_kernel(
        const float* __restrict__ gamma, const float* __restrict__ beta,
        const float* __restrict__ fcW, const float* __restrict__ fcb,
        float* __restrict__ out) {
    __shared__ float sp[NG * DH];
    int t = threadIdx.x;  // 128 threads, thread = feature for stats
    for (int i = t; i < NG * DH; i += 128) sp[i] = g_pool[i];
    __syncthreads();
    float m = 0.f;
    #pragma unroll 4
    for (int g = 0; g < NG; g++) m += sp[g * DH + t];
    m *= (1.f / NG);
    float v = 0.f;
    #pragma unroll 4
    for (int g = 0; g < NG; g++) {
        float d = sp[g * DH + t] - m;
        v += d * d;
    }
    v *= (1.f / NG);
    float rs = rsqrtf(v + 1e-5f);
    float ga = gamma[t], be = beta[t];
    for (int g = 0; g < NG; g++)
        sp[g * DH + t] = (sp[g * DH + t] - m) * rs * ga + be;
    __syncthreads();
    // out[g][j] = sum_c sp[g][c] * fcW[c][j] + fcb[j]
    for (int i = t; i < NG * DLAT; i += 128) {
        int g = i / DLAT, j = i % DLAT;
        float s = fcb[j];
        #pragma unroll 8
        for (int c = 0; c < DH; c++)
            s += sp[g * DH + c] * fcW[c * DLAT + j];
        out[i] = s;
    }
}

// ---------------- launch ----------------------------------------------------
extern "C" void kernel_launch(void* const* d_in, const int* in_sizes, int n_in,
                              void* d_out, int out_size) {
    const float* x     = (const float*)d_in[0];
    const int*   ei    = (const int*)d_in[1];
    const int*   batch = (const int*)d_in[2];
    const float* W0 = (const float*)d_in[3];  const float* b0 = (const float*)d_in[4];
    const float* W1 = (const float*)d_in[5];  const float* b1 = (const float*)d_in[6];
    const float* W2 = (const float*)d_in[7];  const float* b2 = (const float*)d_in[8];
    const float* gamma = (const float*)d_in[9];
    const float* beta  = (const float*)d_in[10];
    const float* fcW   = (const float*)d_in[11];
    const float* fcb   = (const float*)d_in[12];
    float* out = (float*)d_out;

    void *p_deg, *p_cur, *p_delta, *p_pool, *p_h0, *p_h1, *p_feat;
    cudaGetSymbolAddress(&p_deg,   g_deg);
    cudaGetSymbolAddress(&p_cur,   g_cur);
    cudaGetSymbolAddress(&p_delta, g_delta);
    cudaGetSymbolAddress(&p_pool,  g_pool);
    cudaGetSymbolAddress(&p_h0,    g_h0);
    cudaGetSymbolAddress(&p_h1,    g_h1);
    cudaGetSymbolAddress(&p_feat,  g_feat);
    float* h0   = (float*)p_h0;
    float* h1   = (float*)p_h1;
    float* feat = (float*)p_feat;

    cudaMemsetAsync(p_deg,   0, NN * sizeof(int));
    cudaMemsetAsync(p_cur,   0, NN * sizeof(int));
    cudaMemsetAsync(p_delta, 0, sizeof(float));
    cudaMemsetAsync(p_pool,  0, NG * DH * sizeof(float));

    int eblocks = (NE + 1023) / 1024;
    hist_kernel<<<eblocks, 1024>>>(ei);
    scan_kernel<<<1, 1024>>>();
    scatter_kernel<<<eblocks, 1024>>>(ei);
    delta_kernel<<<128, 256>>>();

    int gblocks = (NN + BM - 1) / BM;

    // layer 0: x -> h0
    agg_feat_kernel<<<NN, 128>>>(x, feat);
    gemm_relu_kernel<<<gblocks, 256>>>(feat, W0, b0, h0, NN);
    // layer 1: h0 -> h1
    agg_feat_kernel<<<NN, 128>>>(h0, feat);
    gemm_relu_kernel<<<gblocks, 256>>>(feat, W1, b1, h1, NN);
    // layer 2: h1 -> h0
    agg_feat_kernel<<<NN, 128>>>(h1, feat);
    gemm_relu_kernel<<<gblocks, 256>>>(feat, W2, b2, h0, NN);

    pool_kernel<<<(NN + POOL_NB - 1) / POOL_NB, 128>>>(h0, batch);
    bnfc_kernel<<<1, 128>>>(gamma, beta, fcW, fcb, out);
}

// round 3
// speedup vs baseline: 1.9092x; 1.9092x over previous
#include <cuda_runtime.h>
#include <cuda_bf16.h>
#include <math.h>

// Problem constants (fixed by the reference)
#define NN 50000
#define NE 600000
#define NG 64
#define DH 128
#define DCAT 1664          // 13 * 128
#define DLAT 64
#define K2TOT (DCAT / 2)   // 832 packed k-pairs

// ---------------- scratch (device globals; no allocation allowed) ----------
__device__ int   g_deg[NN];
__device__ int   g_off[NN + 1];
__device__ int   g_cur[NN];
__device__ int   g_csr[NE];
__device__ float g_delta[1];
__device__ float g_h0[(size_t)NN * DH];
__device__ float g_h1[(size_t)NN * DH];
__device__ float g_feat[(size_t)NN * DCAT];
__device__ float g_pool[NG * DH];
__device__ unsigned g_wh[3 * K2TOT * DH];   // packed bf16 hi pairs of W0,W1,W2
__device__ unsigned g_wl[3 * K2TOT * DH];   // packed bf16 lo pairs

// ---------------- bf16 split helpers ---------------------------------------
__device__ __forceinline__ void split_pair(float f0, float f1,
                                           unsigned& hi, unsigned& lo) {
    __nv_bfloat16 h0 = __float2bfloat16_rn(f0);
    __nv_bfloat16 h1 = __float2bfloat16_rn(f1);
    float r0 = f0 - __bfloat162float(h0);
    float r1 = f1 - __bfloat162float(h1);
    __nv_bfloat162 H; H.x = h0; H.y = h1;
    __nv_bfloat162 L = __floats2bfloat162_rn(r0, r1);
    hi = *reinterpret_cast<unsigned*>(&H);
    lo = *reinterpret_cast<unsigned*>(&L);
}

__device__ __forceinline__ void mma_bf16(float* d, const unsigned* a,
                                         const unsigned* b) {
    asm volatile(
        "mma.sync.aligned.m16n8k16.row.col.f32.bf16.bf16.f32 "
        "{%0,%1,%2,%3}, {%4,%5,%6,%7}, {%8,%9}, {%0,%1,%2,%3};\n"
        : "+f"(d[0]), "+f"(d[1]), "+f"(d[2]), "+f"(d[3])
        : "r"(a[0]), "r"(a[1]), "r"(a[2]), "r"(a[3]), "r"(b[0]), "r"(b[1]));
}

// ---------------- graph prep ----------------------------------------------
__global__ void hist_kernel(const int* __restrict__ ei) {
    int e = blockIdx.x * blockDim.x + threadIdx.x;
    int stride = gridDim.x * blockDim.x;
    for (; e < NE; e += stride) {
        int dst = ei[NE + e];
        atomicAdd(&g_deg[dst], 1);
    }
}

__global__ void scan_kernel() {
    __shared__ int sh[1024];
    int t = threadIdx.x;
    int carry = 0;
    for (int base = 0; base < NN; base += 1024) {
        int v = (base + t < NN) ? g_deg[base + t] : 0;
        sh[t] = v;
        __syncthreads();
        #pragma unroll
        for (int s = 1; s < 1024; s <<= 1) {
            int add = (t >= s) ? sh[t - s] : 0;
            __syncthreads();
            sh[t] += add;
            __syncthreads();
        }
        if (base + t < NN) g_off[base + t] = carry + sh[t] - v;
        carry += sh[1023];
        __syncthreads();
    }
    if (t == 0) g_off[NN] = carry;
}

__global__ void scatter_kernel(const int* __restrict__ ei) {
    int e = blockIdx.x * blockDim.x + threadIdx.x;
    int stride = gridDim.x * blockDim.x;
    for (; e < NE; e += stride) {
        int src = ei[e];
        int dst = ei[NE + e];
        int pos = g_off[dst] + atomicAdd(&g_cur[dst], 1);
        g_csr[pos] = src;
    }
}

__global__ void delta_kernel() {
    int i = blockIdx.x * blockDim.x + threadIdx.x;
    int stride = gridDim.x * blockDim.x;
    float s = 0.f;
    for (; i < NN; i += stride) s += logf((float)g_deg[i] + 1.f);
    #pragma unroll
    for (int o = 16; o > 0; o >>= 1) s += __shfl_down_sync(0xffffffffu, s, o);
    __shared__ float sh[32];
    int lane = threadIdx.x & 31, wid = threadIdx.x >> 5;
    if (lane == 0) sh[wid] = s;
    __syncthreads();
    if (wid == 0) {
        float v = (lane < (int)(blockDim.x >> 5)) ? sh[lane] : 0.f;
        #pragma unroll
        for (int o = 16; o > 0; o >>= 1) v += __shfl_down_sync(0xffffffffu, v, o);
        if (lane == 0) atomicAdd(&g_delta[0], v);
    }
}

// split weights into packed bf16 hi/lo (layout: [k2][n] u32)
__global__ void wsplit_kernel(const float* __restrict__ W,
                              unsigned* __restrict__ wh,
                              unsigned* __restrict__ wl) {
    int i = blockIdx.x * blockDim.x + threadIdx.x;
    if (i >= K2TOT * DH) return;
    int k2 = i >> 7, n = i & 127;
    float f0 = W[(size_t)(2 * k2) * DH + n];
    float f1 = W[(size_t)(2 * k2 + 1) * DH + n];
    unsigned h, l;
    split_pair(f0, f1, h, l);
    wh[i] = h; wl[i] = l;
}

// ---------------- per-node aggregation + feature build ---------------------
__global__ __launch_bounds__(128) void agg_feat_kernel(
        const float* __restrict__ h, float* __restrict__ feat) {
    int n = blockIdx.x;
    int t = threadIdx.x;
    int beg = g_off[n], end = g_off[n + 1];
    int d = end - beg;
    float hv = h[(size_t)n * DH + t];
    float s = 0.f, ss = 0.f;
    float mx = __int_as_float(0xff800000);  // -inf
    float mn = __int_as_float(0x7f800000);  // +inf
    __shared__ int ssrc[128];
    for (int base = beg; base < end; base += 128) {
        int cnt = min(128, end - base);
        if (t < cnt) ssrc[t] = g_csr[base + t];
        __syncthreads();
        #pragma unroll 4
        for (int i = 0; i < cnt; i++) {
            float m = h[(size_t)ssrc[i] * DH + t];
            s += m; ss += m * m;
            mx = fmaxf(mx, m); mn = fminf(mn, m);
        }
        __syncthreads();
    }
    float cntf = fmaxf((float)d, 1.f);
    float mean = s / cntf;
    float var  = fmaxf(ss / cntf - mean * mean, 0.f);
    float stdv = sqrtf(var + 1e-5f);
    if (d == 0) { mx = 0.f; mn = 0.f; }
    float delta = g_delta[0] * (1.f / (float)NN);
    float logd = logf((float)d + 1.f);
    float amp = logd / delta;
    float att = delta / fmaxf(logd, 1e-5f);
    size_t b = (size_t)n * DCAT;
    feat[b +    0 + t] = hv;
    feat[b +  128 + t] = mean;
    feat[b +  256 + t] = mx;
    feat[b +  384 + t] = mn;
    feat[b +  512 + t] = stdv;
    feat[b +  640 + t] = mean * amp;
    feat[b +  768 + t] = mx * amp;
    feat[b +  896 + t] = mn * amp;
    feat[b + 1024 + t] = stdv * amp;
    feat[b + 1152 + t] = mean * att;
    feat[b + 1280 + t] = mx * att;
    feat[b + 1408 + t] = mn * att;
    feat[b + 1536 + t] = stdv * att;
}

// ---------------- bf16x3 tensor-core GEMM ----------------------------------
// out[M,128] = relu(A[M,1664] @ W[1664,128] + bias), ~fp32 accuracy via
// 3-term bf16 split: ah*bh + ah*bl + al*bh (fp32 accumulate).
#define GBM 128
#define GBN 128
#define GBK 32
#define GK2 (GBK / 2)          // 16 packed k-pairs per tile
#define KIT (DCAT / GBK)       // 52
#define SPAD 4

__global__ __launch_bounds__(256) void gemm_bf16x3_kernel(
        const float* __restrict__ A,
        const unsigned* __restrict__ Wh, const unsigned* __restrict__ Wl,
        const float* __restrict__ bias, float* __restrict__ out, int M) {
    __shared__ unsigned As_h[GK2][GBM + SPAD];
    __shared__ unsigned As_l[GK2][GBM + SPAD];
    __shared__ unsigned Bs_h[GK2][GBN + SPAD];
    __shared__ unsigned Bs_l[GK2][GBN + SPAD];

    const int tid = threadIdx.x;
    const int lane = tid & 31;
    const int wid = tid >> 5;
    const int warp_m = wid & 3;     // 4 warps along M: 32 rows each
    const int warp_n = wid >> 2;    // 2 warps along N: 64 cols each
    const int row0 = blockIdx.x * GBM;
    const int lr = lane >> 2;       // 0..7
    const int lc = lane & 3;        // 0..3

    float acc[2][8][4];
    #pragma unroll
    for (int i = 0; i < 2; i++)
        #pragma unroll
        for (int j = 0; j < 8; j++)
            #pragma unroll
            for (int c = 0; c < 4; c++) acc[i][j][c] = 0.f;

    float4 ra[4];
    uint4 rbh[2], rbl[2];

    auto ldg_tile = [&](int kt) {
        int k0 = kt * GBK;
        #pragma unroll
        for (int l = 0; l < 4; l++) {
            int idx = tid + l * 256;          // 1024 float4s of A tile
            int r = idx >> 3;                 // 0..127
            int c4 = idx & 7;                 // k-quad
            int row = row0 + r;
            ra[l] = make_float4(0.f, 0.f, 0.f, 0.f);
            if (row < M)
                ra[l] = *(const float4*)&A[(size_t)row * DCAT + k0 + c4 * 4];
        }
        const uint4* ph = (const uint4*)(Wh + (size_t)kt * GK2 * DH);
        const uint4* pl = (const uint4*)(Wl + (size_t)kt * GK2 * DH);
        rbh[0] = ph[tid];       rbh[1] = ph[tid + 256];
        rbl[0] = pl[tid];       rbl[1] = pl[tid + 256];
    };
    auto sts_tile = [&]() {
        #pragma unroll
        for (int l = 0; l < 4; l++) {
            int idx = tid + l * 256;
            int r = idx >> 3;
            int c4 = idx & 7;
            unsigned h0, l0, h1, l1;
            split_pair(ra[l].x, ra[l].y, h0, l0);
            split_pair(ra[l].z, ra[l].w, h1, l1);
            As_h[c4 * 2][r] = h0;     As_l[c4 * 2][r] = l0;
            As_h[c4 * 2 + 1][r] = h1; As_l[c4 * 2 + 1][r] = l1;
        }
        #pragma unroll
        for (int l = 0; l < 2; l++) {
            int idx = tid + l * 256;          // 512 uint4 of B tile
            int k2 = idx >> 5;                // 0..15
            int n4 = idx & 31;
            *(uint4*)&Bs_h[k2][n4 * 4] = rbh[l];
            *(uint4*)&Bs_l[k2][n4 * 4] = rbl[l];
        }
    };

    ldg_tile(0);
    sts_tile();
    __syncthreads();

    for (int kt = 0; kt < KIT; kt++) {
        if (kt + 1 < KIT) ldg_tile(kt + 1);

        #pragma unroll
        for (int kk2 = 0; kk2 < GK2; kk2 += 8) {   // two k16 mma steps
            unsigned ah[2][4], al[2][4];
            #pragma unroll
            for (int mt = 0; mt < 2; mt++) {
                int r = warp_m * 32 + mt * 16 + lr;
                ah[mt][0] = As_h[kk2 + lc][r];
                ah[mt][1] = As_h[kk2 + lc][r + 8];
                ah[mt][2] = As_h[kk2 + 4 + lc][r];
                ah[mt][3] = As_h[kk2 + 4 + lc][r + 8];
                al[mt][0] = As_l[kk2 + lc][r];
                al[mt][1] = As_l[kk2 + lc][r + 8];
                al[mt][2] = As_l[kk2 + 4 + lc][r];
                al[mt][3] = As_l[kk2 + 4 + lc][r + 8];
            }
            #pragma unroll
            for (int nt = 0; nt < 8; nt++) {
                int c = warp_n * 64 + nt * 8 + lr;
                unsigned bh[2], bl[2];
                bh[0] = Bs_h[kk2 + lc][c];
                bh[1] = Bs_h[kk2 + 4 + lc][c];
                bl[0] = Bs_l[kk2 + lc][c];
                bl[1] = Bs_l[kk2 + 4 + lc][c];
                #pragma unroll
                for (int mt = 0; mt < 2; mt++) {
                    mma_bf16(acc[mt][nt], ah[mt], bh);
                    mma_bf16(acc[mt][nt], al[mt], bh);
                    mma_bf16(acc[mt][nt], ah[mt], bl);
                }
            }
        }

        if (kt + 1 < KIT) {
            __syncthreads();
            sts_tile();
            __syncthreads();
        }
    }

    // ---- epilogue: bias + relu ----
    #pragma unroll
    for (int mt = 0; mt < 2; mt++) {
        #pragma unroll
        for (int nt = 0; nt < 8; nt++) {
            int col = warp_n * 64 + nt * 8 + lc * 2;
            float b0 = bias[col], b1 = bias[col + 1];
            int r0 = row0 + warp_m * 32 + mt * 16 + lr;
            if (r0 < M) {
                float2 v;
                v.x = fmaxf(acc[mt][nt][0] + b0, 0.f);
                v.y = fmaxf(acc[mt][nt][1] + b1, 0.f);
                *(float2*)&out[(size_t)r0 * GBN + col] = v;
            }
            int r1 = r0 + 8;
            if (r1 < M) {
                float2 v;
                v.x = fmaxf(acc[mt][nt][2] + b0, 0.f);
                v.y = fmaxf(acc[mt][nt][3] + b1, 0.f);
                *(float2*)&out[(size_t)r1 * GBN + col] = v;
            }
        }
    }
}

// ---------------- pooling (sorted batch -> run-length + few atomics) -------
#define POOL_NB 256
__global__ __launch_bounds__(128) void pool_kernel(
        const float* __restrict__ h, const int* __restrict__ batch) {
    int n0 = blockIdx.x * POOL_NB;
    int t = threadIdx.x;  // feature
    int nend = min(n0 + POOL_NB, NN);
    int cnt = nend - n0;
    __shared__ int sb[POOL_NB];
    for (int i = t; i < cnt; i += 128) sb[i] = batch[n0 + i];
    __syncthreads();
    float acc = 0.f;
    int cur = sb[0];
    for (int i = 0; i < cnt; i++) {
        int b = sb[i];
        if (b != cur) {
            atomicAdd(&g_pool[cur * DH + t], acc);
            acc = 0.f; cur = b;
        }
        acc += h[(size_t)(n0 + i) * DH + t];
    }
    atomicAdd(&g_pool[cur * DH + t], acc);
}

// ---------------- batchnorm (over graphs) + final FC ------------------------
__global__ __launch_bounds__(128) void bnfc_kernel(
        const float* __restrict__ gamma, const float* __restrict__ beta,
        const float* __restrict__ fcW, const float* __restrict__ fcb,
        float* __restrict__ out) {
    __shared__ float sp[NG * DH];
    int t = threadIdx.x;
    for (int i = t; i < NG * DH; i += 128) sp[i] = g_pool[i];
    __syncthreads();
    float m = 0.f;
    #pragma unroll 4
    for (int g = 0; g < NG; g++) m += sp[g * DH + t];
    m *= (1.f / NG);
    float v = 0.f;
    #pragma unroll 4
    for (int g = 0; g < NG; g++) {
        float d = sp[g * DH + t] - m;
        v += d * d;
    }
    v *= (1.f / NG);
    float rs = rsqrtf(v + 1e-5f);
    float ga = gamma[t], be = beta[t];
    for (int g = 0; g < NG; g++)
        sp[g * DH + t] = (sp[g * DH + t] - m) * rs * ga + be;
    __syncthreads();
    for (int i = t; i < NG * DLAT; i += 128) {
        int g = i / DLAT, j = i % DLAT;
        float s = fcb[j];
        #pragma unroll 8
        for (int c = 0; c < DH; c++)
            s += sp[g * DH + c] * fcW[c * DLAT + j];
        out[i] = s;
    }
}

// ---------------- launch ----------------------------------------------------
extern "C" void kernel_launch(void* const* d_in, const int* in_sizes, int n_in,
                              void* d_out, int out_size) {
    const float* x     = (const float*)d_in[0];
    const int*   ei    = (const int*)d_in[1];
    const int*   batch = (const int*)d_in[2];
    const float* W0 = (const float*)d_in[3];  const float* b0 = (const float*)d_in[4];
    const float* W1 = (const float*)d_in[5];  const float* b1 = (const float*)d_in[6];
    const float* W2 = (const float*)d_in[7];  const float* b2 = (const float*)d_in[8];
    const float* gamma = (const float*)d_in[9];
    const float* beta  = (const float*)d_in[10];
    const float* fcW   = (const float*)d_in[11];
    const float* fcb   = (const float*)d_in[12];
    float* out = (float*)d_out;

    void *p_deg, *p_cur, *p_delta, *p_pool, *p_h0, *p_h1, *p_feat, *p_wh, *p_wl;
    cudaGetSymbolAddress(&p_deg,   g_deg);
    cudaGetSymbolAddress(&p_cur,   g_cur);
    cudaGetSymbolAddress(&p_delta, g_delta);
    cudaGetSymbolAddress(&p_pool,  g_pool);
    cudaGetSymbolAddress(&p_h0,    g_h0);
    cudaGetSymbolAddress(&p_h1,    g_h1);
    cudaGetSymbolAddress(&p_feat,  g_feat);
    cudaGetSymbolAddress(&p_wh,    g_wh);
    cudaGetSymbolAddress(&p_wl,    g_wl);
    float* h0   = (float*)p_h0;
    float* h1   = (float*)p_h1;
    float* feat = (float*)p_feat;
    unsigned* wh = (unsigned*)p_wh;
    unsigned* wl = (unsigned*)p_wl;

    cudaMemsetAsync(p_deg,   0, NN * sizeof(int));
    cudaMemsetAsync(p_cur,   0, NN * sizeof(int));
    cudaMemsetAsync(p_delta, 0, sizeof(float));
    cudaMemsetAsync(p_pool,  0, NG * DH * sizeof(float));

    const int WSZ = K2TOT * DH;            // 106496 u32 per layer
    int wblocks = (WSZ + 255) / 256;
    wsplit_kernel<<<wblocks, 256>>>(W0, wh,            wl);
    wsplit_kernel<<<wblocks, 256>>>(W1, wh + WSZ,      wl + WSZ);
    wsplit_kernel<<<wblocks, 256>>>(W2, wh + 2 * WSZ,  wl + 2 * WSZ);

    int eblocks = (NE + 1023) / 1024;
    hist_kernel<<<eblocks, 1024>>>(ei);
    scan_kernel<<<1, 1024>>>();
    scatter_kernel<<<eblocks, 1024>>>(ei);
    delta_kernel<<<128, 256>>>();

    int gblocks = (NN + GBM - 1) / GBM;

    // layer 0: x -> h0
    agg_feat_kernel<<<NN, 128>>>(x, feat);
    gemm_bf16x3_kernel<<<gblocks, 256>>>(feat, wh, wl, b0, h0, NN);
    // layer 1: h0 -> h1
    agg_feat_kernel<<<NN, 128>>>(h0, feat);
    gemm_bf16x3_kernel<<<gblocks, 256>>>(feat, wh + WSZ, wl + WSZ, b1, h1, NN);
    // layer 2: h1 -> h0
    agg_feat_kernel<<<NN, 128>>>(h1, feat);
    gemm_bf16x3_kernel<<<gblocks, 256>>>(feat, wh + 2 * WSZ, wl + 2 * WSZ, b2, h0, NN);

    pool_kernel<<<(NN + POOL_NB - 1) / POOL_NB, 128>>>(h0, batch);
    bnfc_kernel<<<1, 128>>>(gamma, beta, fcW, fcb, out);
}

// round 5
// speedup vs baseline: 2.0521x; 1.0748x over previous
#include <cuda_runtime.h>
#include <cuda_bf16.h>
#include <math.h>
#include <stdint.h>

// Problem constants (fixed by the reference)
#define NN 50000
#define NE 600000
#define NG 64
#define DH 128
#define DCAT 1664          // 13 * 128
#define DLAT 64
#define K2TOT 832          // DCAT/2 packed bf16 pairs per row
#define NT 52              // k-tiles of 32 (16 pairs)

// ---------------- device scratch (no allocation allowed) -------------------
__device__ int   g_deg[NN];
__device__ int   g_off[NN + 1];
__device__ int   g_cur[NN];
__device__ int   g_csr[NE];
__device__ float g_delta[1];
__device__ float g_h0[(size_t)NN * DH];
__device__ float g_h1[(size_t)NN * DH];
__device__ unsigned g_Ah[(size_t)NN * K2TOT];   // A image hi (166MB)
__device__ unsigned g_Al[(size_t)NN * K2TOT];   // A image lo
__device__ unsigned g_Wh[3 * NT * 2048];        // W images: [layer][kt][n][16]
__device__ unsigned g_Wl[3 * NT * 2048];
__device__ float g_pool[NG * DH];

// ---------------- helpers ----------------------------------------------------
__device__ __forceinline__ void split_pair(float f0, float f1,
                                           unsigned& hi, unsigned& lo) {
    __nv_bfloat16 h0 = __float2bfloat16_rn(f0);
    __nv_bfloat16 h1 = __float2bfloat16_rn(f1);
    float r0 = f0 - __bfloat162float(h0);
    float r1 = f1 - __bfloat162float(h1);
    __nv_bfloat162 H; H.x = h0; H.y = h1;
    __nv_bfloat162 L = __floats2bfloat162_rn(r0, r1);
    hi = *reinterpret_cast<unsigned*>(&H);
    lo = *reinterpret_cast<unsigned*>(&L);
}

__device__ __forceinline__ void mma_bf16(float* d, const unsigned* a,
                                         const unsigned* b) {
    asm volatile(
        "mma.sync.aligned.m16n8k16.row.col.f32.bf16.bf16.f32 "
        "{%0,%1,%2,%3}, {%4,%5,%6,%7}, {%8,%9}, {%0,%1,%2,%3};\n"
        : "+f"(d[0]), "+f"(d[1]), "+f"(d[2]), "+f"(d[3])
        : "r"(a[0]), "r"(a[1]), "r"(a[2]), "r"(a[3]), "r"(b[0]), "r"(b[1]));
}

__device__ __forceinline__ uint32_t smem_u32(const void* p) {
    uint32_t a;
    asm("{ .reg .u64 t; cvta.to.shared.u64 t, %1; cvt.u32.u64 %0, t; }"
        : "=r"(a) : "l"(p));
    return a;
}
__device__ __forceinline__ void cp16(uint32_t dst, const void* src) {
    asm volatile("cp.async.cg.shared.global [%0], [%1], 16;"
                 :: "r"(dst), "l"(src));
}
#define CP_COMMIT() asm volatile("cp.async.commit_group;" ::: "memory")
#define CP_WAIT0()  asm volatile("cp.async.wait_group 0;" ::: "memory")

// ---------------- graph prep ----------------------------------------------
__global__ void hist_kernel(const int* __restrict__ ei) {
    int e = blockIdx.x * blockDim.x + threadIdx.x;
    int stride = gridDim.x * blockDim.x;
    for (; e < NE; e += stride) atomicAdd(&g_deg[ei[NE + e]], 1);
}

__global__ void scan_kernel() {
    __shared__ int sh[1024];
    int t = threadIdx.x;
    int carry = 0;
    for (int base = 0; base < NN; base += 1024) {
        int v = (base + t < NN) ? g_deg[base + t] : 0;
        sh[t] = v;
        __syncthreads();
        #pragma unroll
        for (int s = 1; s < 1024; s <<= 1) {
            int add = (t >= s) ? sh[t - s] : 0;
            __syncthreads();
            sh[t] += add;
            __syncthreads();
        }
        if (base + t < NN) g_off[base + t] = carry + sh[t] - v;
        carry += sh[1023];
        __syncthreads();
    }
    if (t == 0) g_off[NN] = carry;
}

__global__ void scatter_kernel(const int* __restrict__ ei) {
    int e = blockIdx.x * blockDim.x + threadIdx.x;
    int stride = gridDim.x * blockDim.x;
    for (; e < NE; e += stride) {
        int dst = ei[NE + e];
        int pos = g_off[dst] + atomicAdd(&g_cur[dst], 1);
        g_csr[pos] = ei[e];
    }
}

__global__ void delta_kernel() {
    int i = blockIdx.x * blockDim.x + threadIdx.x;
    int stride = gridDim.x * blockDim.x;
    float s = 0.f;
    for (; i < NN; i += stride) s += logf((float)g_deg[i] + 1.f);
    #pragma unroll
    for (int o = 16; o > 0; o >>= 1) s += __shfl_down_sync(0xffffffffu, s, o);
    __shared__ float sh[32];
    int lane = threadIdx.x & 31, wid = threadIdx.x >> 5;
    if (lane == 0) sh[wid] = s;
    __syncthreads();
    if (wid == 0) {
        float v = (lane < (int)(blockDim.x >> 5)) ? sh[lane] : 0.f;
        #pragma unroll
        for (int o = 16; o > 0; o >>= 1) v += __shfl_down_sync(0xffffffffu, v, o);
        if (lane == 0) atomicAdd(&g_delta[0], v);
    }
}

// Build W images: per layer, per k-tile kt: [n=128][k2=16] u32 hi/lo.
__global__ void wsplit_kernel(const float* __restrict__ W,
                              unsigned* __restrict__ wh,
                              unsigned* __restrict__ wl) {
    int i = blockIdx.x * blockDim.x + threadIdx.x;
    if (i >= NT * 2048) return;
    int kt  = i >> 11;
    int n   = (i >> 4) & 127;
    int k2l = i & 15;
    int kr = 2 * (kt * 16 + k2l);
    unsigned hi, lo;
    split_pair(W[(size_t)kr * DH + n], W[(size_t)(kr + 1) * DH + n], hi, lo);
    wh[i] = hi;
    wl[i] = lo;
}

// ---------------- aggregation -> pre-split A image --------------------------
__global__ __launch_bounds__(128) void agg_kernel(const float* __restrict__ h) {
    int n = blockIdx.x;
    int t = threadIdx.x;
    int beg = g_off[n], end = g_off[n + 1];
    int d = end - beg;
    float hv = h[(size_t)n * DH + t];
    float s = 0.f, ss = 0.f;
    float mx = __int_as_float(0xff800000);
    float mn = __int_as_float(0x7f800000);
    __shared__ int ssrc[128];
    for (int base = beg; base < end; base += 128) {
        int cnt = min(128, end - base);
        if (t < cnt) ssrc[t] = g_csr[base + t];
        __syncthreads();
        #pragma unroll 4
        for (int i = 0; i < cnt; i++) {
            float m = h[(size_t)ssrc[i] * DH + t];
            s += m; ss += m * m;
            mx = fmaxf(mx, m); mn = fminf(mn, m);
        }
        __syncthreads();
    }
    float cntf = fmaxf((float)d, 1.f);
    float mean = s / cntf;
    float var = fmaxf(ss / cntf - mean * mean, 0.f);
    float stdv = sqrtf(var + 1e-5f);
    if (d == 0) { mx = 0.f; mn = 0.f; }
    float dlt = g_delta[0] * (1.f / (float)NN);
    float logd = logf((float)d + 1.f);
    float amp = logd / dlt;
    float att = dlt / fmaxf(logd, 1e-5f);

    __shared__ float sf[640];
    sf[t] = hv;
    sf[128 + t] = mean;
    sf[256 + t] = mx;
    sf[384 + t] = mn;
    sf[512 + t] = stdv;
    __syncthreads();

    size_t rowb = (size_t)n * K2TOT;
    for (int p = t; p < K2TOT; p += 128) {
        int f = 2 * p;
        float v0, v1;
        if (f < 640)        { v0 = sf[f];          v1 = sf[f + 1]; }
        else if (f < 1152)  { v0 = sf[f - 512] * amp;  v1 = sf[f - 511] * amp; }
        else                { v0 = sf[f - 1024] * att; v1 = sf[f - 1023] * att; }
        unsigned hi, lo;
        split_pair(v0, v1, hi, lo);
        g_Ah[rowb + p] = hi;
        g_Al[rowb + p] = lo;
    }
}

// ---------------- bf16x3 tensor-core GEMM (cp.async double-buffered) --------
// out[M,128] = relu(A[M,1664] @ W[1664,128] + bias)
// smem per stage: Ah/Al/Bh/Bl each [128][20] u32 (stride-20 pad: conflict-free)
#define STG_U32 10240              // 4 * 128 * 20
#define SMEM_BYTES (2 * STG_U32 * 4)

__global__ __launch_bounds__(256, 2) void gemm_cp_kernel(
        const unsigned* __restrict__ Ah, const unsigned* __restrict__ Al,
        const unsigned* __restrict__ Wh, const unsigned* __restrict__ Wl,
        const float* __restrict__ bias, float* __restrict__ out) {
    extern __shared__ unsigned smem_u[];
    const uint32_t sb = smem_u32(smem_u);

    const int tid = threadIdx.x;
    const int lane = tid & 31;
    const int wid = tid >> 5;
    const int warp_m = wid & 3;     // 4 warps x 32 rows
    const int warp_n = wid >> 2;    // 2 warps x 64 cols
    const int lr = lane >> 2;       // 0..7
    const int lc = lane & 3;        // 0..3
    const int row0 = blockIdx.x * 128;

    float acc[2][8][4];
    #pragma unroll
    for (int i = 0; i < 2; i++)
        #pragma unroll
        for (int j = 0; j < 8; j++)
            #pragma unroll
            for (int c = 0; c < 4; c++) acc[i][j][c] = 0.f;

    auto load_tile = [&](int kt, int s) {
        uint32_t sbase = sb + s * (STG_U32 * 4);
        #pragma unroll
        for (int c = 0; c < 8; c++) {
            int idx = c * 256 + tid;
            int buf = idx >> 9;             // 0:Ah 1:Al 2:Bh 3:Bl
            int rem = idx & 511;
            int row = rem >> 2;
            int q = rem & 3;
            uint32_t dst = sbase + (buf * 2560 + row * 20 + q * 4) * 4;
            const unsigned* src;
            if (buf < 2) {
                int node = row0 + row;
                if (node >= NN) node = NN - 1;
                src = (buf == 0 ? Ah : Al) + (size_t)node * K2TOT + kt * 16 + q * 4;
            } else {
                src = (buf == 2 ? Wh : Wl) + ((size_t)kt * 128 + row) * 16 + q * 4;
            }
            cp16(dst, src);
        }
        CP_COMMIT();
    };

    load_tile(0, 0);

    for (int kt = 0; kt < NT; kt++) {
        CP_WAIT0();
        __syncthreads();
        if (kt + 1 < NT) load_tile(kt + 1, (kt + 1) & 1);

        const unsigned* As_h = smem_u + (kt & 1) * STG_U32;
        const unsigned* As_l = As_h + 2560;
        const unsigned* Bs_h = As_h + 5120;
        const unsigned* Bs_l = As_h + 7680;

        #pragma unroll
        for (int kb = 0; kb < 16; kb += 8) {     // two k16 steps
            unsigned ah[2][4], al[2][4];
            #pragma unroll
            for (int mt = 0; mt < 2; mt++) {
                int m0 = warp_m * 32 + mt * 16;
                ah[mt][0] = As_h[(m0 + lr) * 20 + kb + lc];
                ah[mt][1] = As_h[(m0 + 8 + lr) * 20 + kb + lc];
                ah[mt][2] = As_h[(m0 + lr) * 20 + kb + 4 + lc];
                ah[mt][3] = As_h[(m0 + 8 + lr) * 20 + kb + 4 + lc];
                al[mt][0] = As_l[(m0 + lr) * 20 + kb + lc];
                al[mt][1] = As_l[(m0 + 8 + lr) * 20 + kb + lc];
                al[mt][2] = As_l[(m0 + lr) * 20 + kb + 4 + lc];
                al[mt][3] = As_l[(m0 + 8 + lr) * 20 + kb + 4 + lc];
            }
            #pragma unroll
            for (int nt = 0; nt < 8; nt++) {
                int n0 = warp_n * 64 + nt * 8 + lr;
                unsigned bh[2], bl[2];
                bh[0] = Bs_h[n0 * 20 + kb + lc];
                bh[1] = Bs_h[n0 * 20 + kb + 4 + lc];
                bl[0] = Bs_l[n0 * 20 + kb + lc];
                bl[1] = Bs_l[n0 * 20 + kb + 4 + lc];
                #pragma unroll
                for (int mt = 0; mt < 2; mt++) {
                    mma_bf16(acc[mt][nt], ah[mt], bh);
                    mma_bf16(acc[mt][nt], al[mt], bh);
                    mma_bf16(acc[mt][nt], ah[mt], bl);
                }
            }
        }
        __syncthreads();
    }

    // ---- epilogue: bias + relu ----
    #pragma unroll
    for (int mt = 0; mt < 2; mt++) {
        #pragma unroll
        for (int nt = 0; nt < 8; nt++) {
            int col = warp_n * 64 + nt * 8 + lc * 2;
            float b0 = bias[col], b1 = bias[col + 1];
            int r0 = row0 + warp_m * 32 + mt * 16 + lr;
            if (r0 < NN) {
                float2 v;
                v.x = fmaxf(acc[mt][nt][0] + b0, 0.f);
                v.y = fmaxf(acc[mt][nt][1] + b1, 0.f);
                *(float2*)&out[(size_t)r0 * DH + col] = v;
            }
            int r1 = r0 + 8;
            if (r1 < NN) {
                float2 v;
                v.x = fmaxf(acc[mt][nt][2] + b0, 0.f);
                v.y = fmaxf(acc[mt][nt][3] + b1, 0.f);
                *(float2*)&out[(size_t)r1 * DH + col] = v;
            }
        }
    }
}

// ---------------- pooling + bn/fc --------------------------------------------
#define POOL_NB 256
__global__ __launch_bounds__(128) void pool_kernel(
        const float* __restrict__ h, const int* __restrict__ batch) {
    int n0 = blockIdx.x * POOL_NB;
    int t = threadIdx.x;
    int nend = min(n0 + POOL_NB, NN);
    int cnt = nend - n0;
    __shared__ int sbm[POOL_NB];
    for (int i = t; i < cnt; i += 128) sbm[i] = batch[n0 + i];
    __syncthreads();
    float acc = 0.f;
    int cur = sbm[0];
    for (int i = 0; i < cnt; i++) {
        int b = sbm[i];
        if (b != cur) {
            atomicAdd(&g_pool[cur * DH + t], acc);
            acc = 0.f; cur = b;
        }
        acc += h[(size_t)(n0 + i) * DH + t];
    }
    atomicAdd(&g_pool[cur * DH + t], acc);
}

__global__ __launch_bounds__(128) void bnfc_kernel(
        const float* __restrict__ gamma, const float* __restrict__ beta,
        const float* __restrict__ fcW, const float* __restrict__ fcb,
        float* __restrict__ out) {
    __shared__ float sp[NG * DH];
    int t = threadIdx.x;
    for (int i = t; i < NG * DH; i += 128) sp[i] = g_pool[i];
    __syncthreads();
    float m = 0.f;
    #pragma unroll 4
    for (int g = 0; g < NG; g++) m += sp[g * DH + t];
    m *= (1.f / NG);
    float v = 0.f;
    #pragma unroll 4
    for (int g = 0; g < NG; g++) { float d = sp[g * DH + t] - m; v += d * d; }
    v *= (1.f / NG);
    float rs = rsqrtf(v + 1e-5f);
    float ga = gamma[t], be = beta[t];
    for (int g = 0; g < NG; g++)
        sp[g * DH + t] = (sp[g * DH + t] - m) * rs * ga + be;
    __syncthreads();
    for (int i = t; i < NG * DLAT; i += 128) {
        int g = i / DLAT, j = i % DLAT;
        float s = fcb[j];
        #pragma unroll 8
        for (int c = 0; c < DH; c++) s += sp[g * DH + c] * fcW[c * DLAT + j];
        out[i] = s;
    }
}

// ---------------- launch ------------------------------------------------------
extern "C" void kernel_launch(void* const* d_in, const int* in_sizes, int n_in,
                              void* d_out, int out_size) {
    const float* x     = (const float*)d_in[0];
    const int*   ei    = (const int*)d_in[1];
    const int*   batch = (const int*)d_in[2];
    const float* W0 = (const float*)d_in[3];  const float* b0 = (const float*)d_in[4];
    const float* W1 = (const float*)d_in[5];  const float* b1 = (const float*)d_in[6];
    const float* W2 = (const float*)d_in[7];  const float* b2 = (const float*)d_in[8];
    const float* gamma = (const float*)d_in[9];
    const float* beta  = (const float*)d_in[10];
    const float* fcW   = (const float*)d_in[11];
    const float* fcb   = (const float*)d_in[12];
    float* out = (float*)d_out;

    void *p_deg, *p_cur, *p_delta, *p_pool, *p_h0, *p_h1, *p_ah, *p_al, *p_wh, *p_wl;
    cudaGetSymbolAddress(&p_deg,   g_deg);
    cudaGetSymbolAddress(&p_cur,   g_cur);
    cudaGetSymbolAddress(&p_delta, g_delta);
    cudaGetSymbolAddress(&p_pool,  g_pool);
    cudaGetSymbolAddress(&p_h0,    g_h0);
    cudaGetSymbolAddress(&p_h1,    g_h1);
    cudaGetSymbolAddress(&p_ah,    g_Ah);
    cudaGetSymbolAddress(&p_al,    g_Al);
    cudaGetSymbolAddress(&p_wh,    g_Wh);
    cudaGetSymbolAddress(&p_wl,    g_Wl);
    float* h0 = (float*)p_h0;
    float* h1 = (float*)p_h1;
    unsigned* ah = (unsigned*)p_ah;
    unsigned* al = (unsigned*)p_al;
    unsigned* wh = (unsigned*)p_wh;
    unsigned* wl = (unsigned*)p_wl;

    cudaFuncSetAttribute(gemm_cp_kernel,
                         cudaFuncAttributeMaxDynamicSharedMemorySize, SMEM_BYTES);

    cudaMemsetAsync(p_deg,   0, NN * sizeof(int));
    cudaMemsetAsync(p_cur,   0, NN * sizeof(int));
    cudaMemsetAsync(p_delta, 0, sizeof(float));
    cudaMemsetAsync(p_pool,  0, NG * DH * sizeof(float));

    const int WSZ = NT * 2048;
    int wblocks = (WSZ + 255) / 256;
    wsplit_kernel<<<wblocks, 256>>>(W0, wh,           wl);
    wsplit_kernel<<<wblocks, 256>>>(W1, wh + WSZ,     wl + WSZ);
    wsplit_kernel<<<wblocks, 256>>>(W2, wh + 2 * WSZ, wl + 2 * WSZ);

    int eblocks = (NE + 1023) / 1024;
    hist_kernel<<<eblocks, 1024>>>(ei);
    scan_kernel<<<1, 1024>>>();
    scatter_kernel<<<eblocks, 1024>>>(ei);
    delta_kernel<<<128, 256>>>();

    int gblocks = (NN + 127) / 128;

    agg_kernel<<<NN, 128>>>(x);
    gemm_cp_kernel<<<gblocks, 256, SMEM_BYTES>>>(ah, al, wh, wl, b0, h0);
    agg_kernel<<<NN, 128>>>(h0);
    gemm_cp_kernel<<<gblocks, 256, SMEM_BYTES>>>(ah, al, wh + WSZ, wl + WSZ, b1, h1);
    agg_kernel<<<NN, 128>>>(h1);
    gemm_cp_kernel<<<gblocks, 256, SMEM_BYTES>>>(ah, al, wh + 2 * WSZ, wl + 2 * WSZ, b2, h0);

    pool_kernel<<<(NN + POOL_NB - 1) / POOL_NB, 128>>>(h0, batch);
    bnfc_kernel<<<1, 128>>>(gamma, beta, fcW, fcb, out);
}

// round 6
// speedup vs baseline: 2.1588x; 1.0520x over previous
#include <cuda_runtime.h>
#include <cuda_bf16.h>
#include <math.h>
#include <stdint.h>

// Problem constants (fixed by the reference)
#define NN 50000
#define NE 600000
#define NG 64
#define DH 128
#define DLAT 64

// GEMM factorization: feat@W = h@Wh + agg@W1 + amp*(agg@W2) + att*(agg@W3)
#define KH2 64          // h image packed pairs per row (128 cols)
#define KA2 256         // agg image packed pairs per row (512 cols)
#define NTA 4           // h k-tiles (16 pairs each)
#define NTB 16          // agg k-tiles
#define NJ  20          // jobs per block
#define WLAYER 212992   // u32 per layer W image: 4*2*2048 + 16*6*2048

// ---------------- device scratch (no allocation allowed) -------------------
__device__ int   g_deg[NN];
__device__ int   g_off[NN + 1];
__device__ int   g_cur[NN];
__device__ int   g_csr[NE];
__device__ float g_delta[1];
__device__ float g_h0[(size_t)NN * DH];
__device__ float g_h1[(size_t)NN * DH];
__device__ unsigned g_Hh[(size_t)NN * KH2];   // split h image hi (12.8MB)
__device__ unsigned g_Hl[(size_t)NN * KH2];
__device__ unsigned g_Agh[(size_t)NN * KA2];  // split agg image hi (51.2MB)
__device__ unsigned g_Agl[(size_t)NN * KA2];
__device__ unsigned g_W[3 * WLAYER];          // packed W images (2.5MB)
__device__ float g_pool[NG * DH];

// ---------------- helpers ----------------------------------------------------
__device__ __forceinline__ void split_pair(float f0, float f1,
                                           unsigned& hi, unsigned& lo) {
    __nv_bfloat16 h0 = __float2bfloat16_rn(f0);
    __nv_bfloat16 h1 = __float2bfloat16_rn(f1);
    float r0 = f0 - __bfloat162float(h0);
    float r1 = f1 - __bfloat162float(h1);
    __nv_bfloat162 H; H.x = h0; H.y = h1;
    __nv_bfloat162 L = __floats2bfloat162_rn(r0, r1);
    hi = *reinterpret_cast<unsigned*>(&H);
    lo = *reinterpret_cast<unsigned*>(&L);
}

__device__ __forceinline__ void mma_bf16(float* d, const unsigned* a,
                                         const unsigned* b) {
    asm volatile(
        "mma.sync.aligned.m16n8k16.row.col.f32.bf16.bf16.f32 "
        "{%0,%1,%2,%3}, {%4,%5,%6,%7}, {%8,%9}, {%0,%1,%2,%3};\n"
        : "+f"(d[0]), "+f"(d[1]), "+f"(d[2]), "+f"(d[3])
        : "r"(a[0]), "r"(a[1]), "r"(a[2]), "r"(a[3]), "r"(b[0]), "r"(b[1]));
}

__device__ __forceinline__ uint32_t smem_u32(const void* p) {
    uint32_t a;
    asm("{ .reg .u64 t; cvta.to.shared.u64 t, %1; cvt.u32.u64 %0, t; }"
        : "=r"(a) : "l"(p));
    return a;
}
__device__ __forceinline__ void cp16(uint32_t dst, const void* src) {
    asm volatile("cp.async.cg.shared.global [%0], [%1], 16;"
                 :: "r"(dst), "l"(src));
}
#define CP_COMMIT() asm volatile("cp.async.commit_group;" ::: "memory")
#define CP_WAIT0()  asm volatile("cp.async.wait_group 0;" ::: "memory")

// ---------------- graph prep ----------------------------------------------
__global__ void hist_kernel(const int* __restrict__ ei) {
    int e = blockIdx.x * blockDim.x + threadIdx.x;
    int stride = gridDim.x * blockDim.x;
    for (; e < NE; e += stride) atomicAdd(&g_deg[ei[NE + e]], 1);
}

__global__ void scan_kernel() {
    __shared__ int sh[1024];
    int t = threadIdx.x;
    int carry = 0;
    for (int base = 0; base < NN; base += 1024) {
        int v = (base + t < NN) ? g_deg[base + t] : 0;
        sh[t] = v;
        __syncthreads();
        #pragma unroll
        for (int s = 1; s < 1024; s <<= 1) {
            int add = (t >= s) ? sh[t - s] : 0;
            __syncthreads();
            sh[t] += add;
            __syncthreads();
        }
        if (base + t < NN) g_off[base + t] = carry + sh[t] - v;
        carry += sh[1023];
        __syncthreads();
    }
    if (t == 0) g_off[NN] = carry;
}

__global__ void scatter_kernel(const int* __restrict__ ei) {
    int e = blockIdx.x * blockDim.x + threadIdx.x;
    int stride = gridDim.x * blockDim.x;
    for (; e < NE; e += stride) {
        int dst = ei[NE + e];
        int pos = g_off[dst] + atomicAdd(&g_cur[dst], 1);
        g_csr[pos] = ei[e];
    }
}

__global__ void delta_kernel() {
    int i = blockIdx.x * blockDim.x + threadIdx.x;
    int stride = gridDim.x * blockDim.x;
    float s = 0.f;
    for (; i < NN; i += stride) s += logf((float)g_deg[i] + 1.f);
    #pragma unroll
    for (int o = 16; o > 0; o >>= 1) s += __shfl_down_sync(0xffffffffu, s, o);
    __shared__ float sh[32];
    int lane = threadIdx.x & 31, wid = threadIdx.x >> 5;
    if (lane == 0) sh[wid] = s;
    __syncthreads();
    if (wid == 0) {
        float v = (lane < (int)(blockDim.x >> 5)) ? sh[lane] : 0.f;
        #pragma unroll
        for (int o = 16; o > 0; o >>= 1) v += __shfl_down_sync(0xffffffffu, v, o);
        if (lane == 0) atomicAdd(&g_delta[0], v);
    }
}

// ---------------- W pre-pack --------------------------------------------------
// Layout per layer (u32): [kt=0..3: Wh hi(128x16), lo] then
// [kt=0..15: W1 hi,lo; W2 hi,lo; W3 hi,lo], each buffer [n=128][k2=16].
__global__ void wsplit_kernel(const float* __restrict__ W,
                              unsigned* __restrict__ wdst) {
    int i = blockIdx.x * blockDim.x + threadIdx.x;
    if (i >= 832 * 128) return;
    int kr2 = i >> 7;
    int n = i & 127;
    int kr = 2 * kr2;
    unsigned hi, lo;
    split_pair(W[(size_t)kr * DH + n], W[(size_t)(kr + 1) * DH + n], hi, lo);
    int base;
    int loc;
    if (kr2 < 64) {                       // h segment (rows 0..127)
        int kt = kr2 >> 4; loc = kr2 & 15;
        base = kt * 4096;
    } else {                              // agg segments
        int p = kr2 - 64;                 // 0..767
        int w = p >> 8;                   // 0..2  (W1,W2,W3)
        int q = p & 255;
        int kt = q >> 4; loc = q & 15;
        base = 16384 + kt * 12288 + w * 4096;
    }
    wdst[base + n * 16 + loc] = hi;
    wdst[base + 2048 + n * 16 + loc] = lo;
}

// split x (layer-0 input) into the h image
__global__ void xsplit_kernel(const float* __restrict__ x) {
    int i = blockIdx.x * blockDim.x + threadIdx.x;
    if (i >= NN * KH2) return;
    int n = i >> 6, p = i & 63;
    unsigned hi, lo;
    split_pair(x[(size_t)n * DH + 2 * p], x[(size_t)n * DH + 2 * p + 1], hi, lo);
    g_Hh[i] = hi;
    g_Hl[i] = lo;
}

// ---------------- aggregation -> split agg image (512 cols) ------------------
__global__ __launch_bounds__(128) void agg_kernel(const float* __restrict__ h) {
    int n = blockIdx.x;
    int t = threadIdx.x;
    int beg = g_off[n], end = g_off[n + 1];
    int d = end - beg;
    float s = 0.f, ss = 0.f;
    float mx = __int_as_float(0xff800000);
    float mn = __int_as_float(0x7f800000);
    __shared__ int ssrc[128];
    for (int base = beg; base < end; base += 128) {
        int cnt = min(128, end - base);
        if (t < cnt) ssrc[t] = g_csr[base + t];
        __syncthreads();
        #pragma unroll 4
        for (int i = 0; i < cnt; i++) {
            float m = h[(size_t)ssrc[i] * DH + t];
            s += m; ss += m * m;
            mx = fmaxf(mx, m); mn = fminf(mn, m);
        }
        __syncthreads();
    }
    float cntf = fmaxf((float)d, 1.f);
    float mean = s / cntf;
    float var = fmaxf(ss / cntf - mean * mean, 0.f);
    float stdv = sqrtf(var + 1e-5f);
    if (d == 0) { mx = 0.f; mn = 0.f; }

    __shared__ float sf[512];
    sf[t] = mean;
    sf[128 + t] = mx;
    sf[256 + t] = mn;
    sf[384 + t] = stdv;
    __syncthreads();

    size_t rowb = (size_t)n * KA2;
    #pragma unroll
    for (int p = t; p < KA2; p += 128) {
        unsigned hi, lo;
        split_pair(sf[2 * p], sf[2 * p + 1], hi, lo);
        g_Agh[rowb + p] = hi;
        g_Agl[rowb + p] = lo;
    }
}

// ---------------- factorized bf16x3 GEMM -------------------------------------
// out = relu(h@Wh + agg@W1 + amp*(agg@W2) + att*(agg@W3) + bias)
// 384 threads (12 warps 3x4), M-tile 96, warp tile 32x32, 3 acc groups.
#define BMR 96
#define STG 19200       // u32 per stage: A 2*96*20 + B 6*128*20
#define SMEM_BYTES (2 * STG * 4)

__global__ __launch_bounds__(384, 1) void gemm_fact_kernel(
        const unsigned* __restrict__ Wimg, const float* __restrict__ bias,
        float* __restrict__ hout, int write_split) {
    extern __shared__ unsigned smem_u[];
    const uint32_t sb = smem_u32(smem_u);

    const int tid = threadIdx.x;
    const int lane = tid & 31;
    const int wid = tid >> 5;
    const int warp_m = wid >> 2;    // 0..2 (32 rows each)
    const int warp_n = wid & 3;     // 0..3 (32 cols each)
    const int lr = lane >> 2;       // 0..7
    const int lc = lane & 3;        // 0..3
    const int row0 = blockIdx.x * BMR;

    float acc[3][2][4][4];
    #pragma unroll
    for (int g = 0; g < 3; g++)
        #pragma unroll
        for (int mt = 0; mt < 2; mt++)
            #pragma unroll
            for (int nt = 0; nt < 4; nt++)
                #pragma unroll
                for (int c = 0; c < 4; c++) acc[g][mt][nt][c] = 0.f;

    auto load_stage = [&](int j, int s) {
        uint32_t base = sb + s * (STG * 4);
        int nB = (j < 4) ? 1 : 3;
        int kt = (j < 4) ? j : j - 4;
        const unsigned* Ah = (j < 4) ? g_Hh : g_Agh;
        const unsigned* Al = (j < 4) ? g_Hl : g_Agl;
        int K2 = (j < 4) ? KH2 : KA2;
        const unsigned* Bsrc = Wimg + ((j < 4) ? (size_t)j * 4096
                                               : (size_t)16384 + (size_t)kt * 12288);
        int nch = 768 + nB * 1024;
        for (int c = tid; c < nch; c += 384) {
            uint32_t dst;
            const unsigned* src;
            if (c < 768) {
                int half = c >> 9;           // 384 chunks hi, 384 lo? (c/384)
                // careful: 768 = 2*384; use half = c >= 384
                half = (c >= 384) ? 1 : 0;
                int rem = (c >= 384) ? c - 384 : c;
                int row = rem >> 2;
                int q = rem & 3;
                int node = row0 + row;
                if (node >= NN) node = NN - 1;
                src = (half ? Al : Ah) + (size_t)node * K2 + kt * 16 + q * 4;
                dst = base + (half * 1920 + row * 20 + q * 4) * 4;
            } else {
                int b = c - 768;
                int slot = b >> 9;           // 0..(2*nB-1)
                int rem = b & 511;
                int r = rem >> 2;
                int q = rem & 3;
                src = Bsrc + slot * 2048 + r * 16 + q * 4;
                dst = base + (3840 + slot * 2560 + r * 20 + q * 4) * 4;
            }
            cp16(dst, src);
        }
        CP_COMMIT();
    };

    load_stage(0, 0);

    for (int j = 0; j < NJ; j++) {
        CP_WAIT0();
        __syncthreads();
        if (j + 1 < NJ) load_stage(j + 1, (j + 1) & 1);

        const unsigned* st = smem_u + (j & 1) * STG;
        const unsigned* As_h = st;
        const unsigned* As_l = st + 1920;
        const unsigned* Bb = st + 3840;
        int nB = (j < 4) ? 1 : 3;

        #pragma unroll
        for (int kb = 0; kb < 16; kb += 8) {
            unsigned ah[2][4], al[2][4];
            #pragma unroll
            for (int mt = 0; mt < 2; mt++) {
                int m0 = warp_m * 32 + mt * 16;
                ah[mt][0] = As_h[(m0 + lr) * 20 + kb + lc];
                ah[mt][1] = As_h[(m0 + 8 + lr) * 20 + kb + lc];
                ah[mt][2] = As_h[(m0 + lr) * 20 + kb + 4 + lc];
                ah[mt][3] = As_h[(m0 + 8 + lr) * 20 + kb + 4 + lc];
                al[mt][0] = As_l[(m0 + lr) * 20 + kb + lc];
                al[mt][1] = As_l[(m0 + 8 + lr) * 20 + kb + lc];
                al[mt][2] = As_l[(m0 + lr) * 20 + kb + 4 + lc];
                al[mt][3] = As_l[(m0 + 8 + lr) * 20 + kb + 4 + lc];
            }
            for (int w = 0; w < nB; w++) {
                const unsigned* Bh = Bb + w * 5120;
                const unsigned* Bl = Bh + 2560;
                int g = (j < 4) ? 0 : w;
                #pragma unroll
                for (int nt = 0; nt < 4; nt++) {
                    int n0 = warp_n * 32 + nt * 8 + lr;
                    unsigned bh[2], bl[2];
                    bh[0] = Bh[n0 * 20 + kb + lc];
                    bh[1] = Bh[n0 * 20 + kb + 4 + lc];
                    bl[0] = Bl[n0 * 20 + kb + lc];
                    bl[1] = Bl[n0 * 20 + kb + 4 + lc];
                    #pragma unroll
                    for (int mt = 0; mt < 2; mt++) {
                        mma_bf16(acc[g][mt][nt], ah[mt], bh);
                        mma_bf16(acc[g][mt][nt], al[mt], bh);
                        mma_bf16(acc[g][mt][nt], ah[mt], bl);
                    }
                }
            }
        }
        __syncthreads();
    }

    // ---- epilogue ----
    float dlt = g_delta[0] * (1.f / (float)NN);
    float ampv[2][2], attv[2][2];
    #pragma unroll
    for (int mt = 0; mt < 2; mt++)
        #pragma unroll
        for (int rr = 0; rr < 2; rr++) {
            int row = row0 + warp_m * 32 + mt * 16 + lr + rr * 8;
            float a = 0.f, b = 0.f;
            if (row < NN) {
                float logd = logf((float)g_deg[row] + 1.f);
                a = logd / dlt;
                b = dlt / fmaxf(logd, 1e-5f);
            }
            ampv[mt][rr] = a;
            attv[mt][rr] = b;
        }

    #pragma unroll
    for (int mt = 0; mt < 2; mt++) {
        #pragma unroll
        for (int nt = 0; nt < 4; nt++) {
            int col = warp_n * 32 + nt * 8 + lc * 2;
            float b0 = bias[col], b1 = bias[col + 1];
            #pragma unroll
            for (int rr = 0; rr < 2; rr++) {
                int row = row0 + warp_m * 32 + mt * 16 + lr + rr * 8;
                if (row >= NN) continue;
                float amp = ampv[mt][rr], att = attv[mt][rr];
                int i0 = rr * 2;
                float2 v;
                v.x = fmaxf(acc[0][mt][nt][i0] + amp * acc[1][mt][nt][i0]
                            + att * acc[2][mt][nt][i0] + b0, 0.f);
                v.y = fmaxf(acc[0][mt][nt][i0 + 1] + amp * acc[1][mt][nt][i0 + 1]
                            + att * acc[2][mt][nt][i0 + 1] + b1, 0.f);
                *(float2*)&hout[(size_t)row * DH + col] = v;
                if (write_split) {
                    unsigned hi, lo;
                    split_pair(v.x, v.y, hi, lo);
                    g_Hh[(size_t)row * KH2 + (col >> 1)] = hi;
                    g_Hl[(size_t)row * KH2 + (col >> 1)] = lo;
                }
            }
        }
    }
}

// ---------------- pooling + bn/fc --------------------------------------------
#define POOL_NB 256
__global__ __launch_bounds__(128) void pool_kernel(
        const float* __restrict__ h, const int* __restrict__ batch) {
    int n0 = blockIdx.x * POOL_NB;
    int t = threadIdx.x;
    int nend = min(n0 + POOL_NB, NN);
    int cnt = nend - n0;
    __shared__ int sbm[POOL_NB];
    for (int i = t; i < cnt; i += 128) sbm[i] = batch[n0 + i];
    __syncthreads();
    float acc = 0.f;
    int cur = sbm[0];
    for (int i = 0; i < cnt; i++) {
        int b = sbm[i];
        if (b != cur) {
            atomicAdd(&g_pool[cur * DH + t], acc);
            acc = 0.f; cur = b;
        }
        acc += h[(size_t)(n0 + i) * DH + t];
    }
    atomicAdd(&g_pool[cur * DH + t], acc);
}

__global__ __launch_bounds__(128) void bnfc_kernel(
        const float* __restrict__ gamma, const float* __restrict__ beta,
        const float* __restrict__ fcW, const float* __restrict__ fcb,
        float* __restrict__ out) {
    __shared__ float sp[NG * DH];
    int t = threadIdx.x;
    for (int i = t; i < NG * DH; i += 128) sp[i] = g_pool[i];
    __syncthreads();
    float m = 0.f;
    #pragma unroll 4
    for (int g = 0; g < NG; g++) m += sp[g * DH + t];
    m *= (1.f / NG);
    float v = 0.f;
    #pragma unroll 4
    for (int g = 0; g < NG; g++) { float d = sp[g * DH + t] - m; v += d * d; }
    v *= (1.f / NG);
    float rs = rsqrtf(v + 1e-5f);
    float ga = gamma[t], be = beta[t];
    for (int g = 0; g < NG; g++)
        sp[g * DH + t] = (sp[g * DH + t] - m) * rs * ga + be;
    __syncthreads();
    for (int i = t; i < NG * DLAT; i += 128) {
        int g = i / DLAT, j = i % DLAT;
        float s = fcb[j];
        #pragma unroll 8
        for (int c = 0; c < DH; c++) s += sp[g * DH + c] * fcW[c * DLAT + j];
        out[i] = s;
    }
}

// ---------------- launch ------------------------------------------------------
extern "C" void kernel_launch(void* const* d_in, const int* in_sizes, int n_in,
                              void* d_out, int out_size) {
    const float* x     = (const float*)d_in[0];
    const int*   ei    = (const int*)d_in[1];
    const int*   batch = (const int*)d_in[2];
    const float* W0 = (const float*)d_in[3];  const float* b0 = (const float*)d_in[4];
    const float* W1 = (const float*)d_in[5];  const float* b1 = (const float*)d_in[6];
    const float* W2 = (const float*)d_in[7];  const float* b2 = (const float*)d_in[8];
    const float* gamma = (const float*)d_in[9];
    const float* beta  = (const float*)d_in[10];
    const float* fcW   = (const float*)d_in[11];
    const float* fcb   = (const float*)d_in[12];
    float* out = (float*)d_out;

    void *p_deg, *p_cur, *p_delta, *p_pool, *p_h0, *p_h1, *p_w;
    cudaGetSymbolAddress(&p_deg,   g_deg);
    cudaGetSymbolAddress(&p_cur,   g_cur);
    cudaGetSymbolAddress(&p_delta, g_delta);
    cudaGetSymbolAddress(&p_pool,  g_pool);
    cudaGetSymbolAddress(&p_h0,    g_h0);
    cudaGetSymbolAddress(&p_h1,    g_h1);
    cudaGetSymbolAddress(&p_w,     g_W);
    float* h0 = (float*)p_h0;
    float* h1 = (float*)p_h1;
    unsigned* wimg = (unsigned*)p_w;

    cudaFuncSetAttribute(gemm_fact_kernel,
                         cudaFuncAttributeMaxDynamicSharedMemorySize, SMEM_BYTES);

    cudaMemsetAsync(p_deg,   0, NN * sizeof(int));
    cudaMemsetAsync(p_cur,   0, NN * sizeof(int));
    cudaMemsetAsync(p_delta, 0, sizeof(float));
    cudaMemsetAsync(p_pool,  0, NG * DH * sizeof(float));

    int wthreads = 832 * 128;
    int wblocks = (wthreads + 255) / 256;
    wsplit_kernel<<<wblocks, 256>>>(W0, wimg);
    wsplit_kernel<<<wblocks, 256>>>(W1, wimg + WLAYER);
    wsplit_kernel<<<wblocks, 256>>>(W2, wimg + 2 * WLAYER);
    xsplit_kernel<<<(NN * KH2 + 255) / 256, 256>>>(x);

    int eblocks = (NE + 1023) / 1024;
    hist_kernel<<<eblocks, 1024>>>(ei);
    scan_kernel<<<1, 1024>>>();
    scatter_kernel<<<eblocks, 1024>>>(ei);
    delta_kernel<<<128, 256>>>();

    int gblocks = (NN + BMR - 1) / BMR;   // 521

    // layer 0: agg(x), gemm -> h0 (+ split image for layer 1)
    agg_kernel<<<NN, 128>>>(x);
    gemm_fact_kernel<<<gblocks, 384, SMEM_BYTES>>>(wimg, b0, h0, 1);
    // layer 1
    agg_kernel<<<NN, 128>>>(h0);
    gemm_fact_kernel<<<gblocks, 384, SMEM_BYTES>>>(wimg + WLAYER, b1, h1, 1);
    // layer 2 (no split image needed)
    agg_kernel<<<NN, 128>>>(h1);
    gemm_fact_kernel<<<gblocks, 384, SMEM_BYTES>>>(wimg + 2 * WLAYER, b2, h0, 0);

    pool_kernel<<<(NN + POOL_NB - 1) / POOL_NB, 128>>>(h0, batch);
    bnfc_kernel<<<1, 128>>>(gamma, beta, fcW, fcb, out);
}

// round 7
// speedup vs baseline: 2.2062x; 1.0220x over previous
#include <cuda_runtime.h>
#include <cuda_bf16.h>
#include <math.h>
#include <stdint.h>

// Problem constants (fixed by the reference)
#define NN 50000
#define NE 600000
#define NG 64
#define DH 128
#define DLAT 64

// GEMM factorization: feat@W = h@Wh + agg@W1 + amp*(agg@W2) + att*(agg@W3)
#define KH2 64          // h image packed pairs per row (128 cols)
#define KA2 256         // agg image packed pairs per row (512 cols)
#define NJ  20          // jobs per block
#define WLAYER 212992   // u32 per layer W image

// ---------------- device scratch (no allocation allowed) -------------------
__device__ int   g_deg[NN];
__device__ int   g_off[NN + 1];
__device__ int   g_cur[NN];
__device__ int   g_csr[NE];
__device__ float g_delta[1];
__device__ float g_h0[(size_t)NN * DH];
__device__ float g_h1[(size_t)NN * DH];
__device__ unsigned g_Hh[(size_t)NN * KH2];   // split h image hi
__device__ unsigned g_Hl[(size_t)NN * KH2];
__device__ unsigned g_Agh[(size_t)NN * KA2];  // split agg image hi
__device__ unsigned g_Agl[(size_t)NN * KA2];
__device__ unsigned g_W[3 * WLAYER];          // packed W images
__device__ float g_pool[NG * DH];

// ---------------- helpers ----------------------------------------------------
__device__ __forceinline__ void split_pair(float f0, float f1,
                                           unsigned& hi, unsigned& lo) {
    __nv_bfloat16 h0 = __float2bfloat16_rn(f0);
    __nv_bfloat16 h1 = __float2bfloat16_rn(f1);
    float r0 = f0 - __bfloat162float(h0);
    float r1 = f1 - __bfloat162float(h1);
    __nv_bfloat162 H; H.x = h0; H.y = h1;
    __nv_bfloat162 L = __floats2bfloat162_rn(r0, r1);
    hi = *reinterpret_cast<unsigned*>(&H);
    lo = *reinterpret_cast<unsigned*>(&L);
}

__device__ __forceinline__ void mma_bf16(float* d, const unsigned* a,
                                         const unsigned* b) {
    asm volatile(
        "mma.sync.aligned.m16n8k16.row.col.f32.bf16.bf16.f32 "
        "{%0,%1,%2,%3}, {%4,%5,%6,%7}, {%8,%9}, {%0,%1,%2,%3};\n"
        : "+f"(d[0]), "+f"(d[1]), "+f"(d[2]), "+f"(d[3])
        : "r"(a[0]), "r"(a[1]), "r"(a[2]), "r"(a[3]), "r"(b[0]), "r"(b[1]));
}

__device__ __forceinline__ void ldsm4(unsigned& r0, unsigned& r1,
                                      unsigned& r2, unsigned& r3, uint32_t a) {
    asm volatile("ldmatrix.sync.aligned.m8n8.x4.shared.b16 {%0,%1,%2,%3}, [%4];"
                 : "=r"(r0), "=r"(r1), "=r"(r2), "=r"(r3) : "r"(a));
}

__device__ __forceinline__ uint32_t smem_u32(const void* p) {
    uint32_t a;
    asm("{ .reg .u64 t; cvta.to.shared.u64 t, %1; cvt.u32.u64 %0, t; }"
        : "=r"(a) : "l"(p));
    return a;
}
__device__ __forceinline__ void cp16(uint32_t dst, const void* src) {
    asm volatile("cp.async.cg.shared.global [%0], [%1], 16;"
                 :: "r"(dst), "l"(src));
}
#define CP_COMMIT() asm volatile("cp.async.commit_group;" ::: "memory")
#define CP_WAIT0()  asm volatile("cp.async.wait_group 0;" ::: "memory")

// ---------------- graph prep ----------------------------------------------
__global__ void hist_kernel(const int* __restrict__ ei) {
    int e = blockIdx.x * blockDim.x + threadIdx.x;
    int stride = gridDim.x * blockDim.x;
    for (; e < NE; e += stride) atomicAdd(&g_deg[ei[NE + e]], 1);
}

__global__ void scan_kernel() {
    __shared__ int sh[1024];
    int t = threadIdx.x;
    int carry = 0;
    for (int base = 0; base < NN; base += 1024) {
        int v = (base + t < NN) ? g_deg[base + t] : 0;
        sh[t] = v;
        __syncthreads();
        #pragma unroll
        for (int s = 1; s < 1024; s <<= 1) {
            int add = (t >= s) ? sh[t - s] : 0;
            __syncthreads();
            sh[t] += add;
            __syncthreads();
        }
        if (base + t < NN) g_off[base + t] = carry + sh[t] - v;
        carry += sh[1023];
        __syncthreads();
    }
    if (t == 0) g_off[NN] = carry;
}

__global__ void scatter_kernel(const int* __restrict__ ei) {
    int e = blockIdx.x * blockDim.x + threadIdx.x;
    int stride = gridDim.x * blockDim.x;
    for (; e < NE; e += stride) {
        int dst = ei[NE + e];
        int pos = g_off[dst] + atomicAdd(&g_cur[dst], 1);
        g_csr[pos] = ei[e];
    }
}

__global__ void delta_kernel() {
    int i = blockIdx.x * blockDim.x + threadIdx.x;
    int stride = gridDim.x * blockDim.x;
    float s = 0.f;
    for (; i < NN; i += stride) s += logf((float)g_deg[i] + 1.f);
    #pragma unroll
    for (int o = 16; o > 0; o >>= 1) s += __shfl_down_sync(0xffffffffu, s, o);
    __shared__ float sh[32];
    int lane = threadIdx.x & 31, wid = threadIdx.x >> 5;
    if (lane == 0) sh[wid] = s;
    __syncthreads();
    if (wid == 0) {
        float v = (lane < (int)(blockDim.x >> 5)) ? sh[lane] : 0.f;
        #pragma unroll
        for (int o = 16; o > 0; o >>= 1) v += __shfl_down_sync(0xffffffffu, v, o);
        if (lane == 0) atomicAdd(&g_delta[0], v);
    }
}

// ---------------- W pre-pack --------------------------------------------------
__global__ void wsplit_kernel(const float* __restrict__ W,
                              unsigned* __restrict__ wdst) {
    int i = blockIdx.x * blockDim.x + threadIdx.x;
    if (i >= 832 * 128) return;
    int kr2 = i >> 7;
    int n = i & 127;
    int kr = 2 * kr2;
    unsigned hi, lo;
    split_pair(W[(size_t)kr * DH + n], W[(size_t)(kr + 1) * DH + n], hi, lo);
    int base, loc;
    if (kr2 < 64) {
        int kt = kr2 >> 4; loc = kr2 & 15;
        base = kt * 4096;
    } else {
        int p = kr2 - 64;
        int w = p >> 8;
        int q = p & 255;
        int kt = q >> 4; loc = q & 15;
        base = 16384 + kt * 12288 + w * 4096;
    }
    wdst[base + n * 16 + loc] = hi;
    wdst[base + 2048 + n * 16 + loc] = lo;
}

__global__ void xsplit_kernel(const float* __restrict__ x) {
    int i = blockIdx.x * blockDim.x + threadIdx.x;
    if (i >= NN * KH2) return;
    int n = i >> 6, p = i & 63;
    unsigned hi, lo;
    split_pair(x[(size_t)n * DH + 2 * p], x[(size_t)n * DH + 2 * p + 1], hi, lo);
    g_Hh[i] = hi;
    g_Hl[i] = lo;
}

// ---------------- aggregation -> split agg image (512 cols) ------------------
__global__ __launch_bounds__(128) void agg_kernel(const float* __restrict__ h) {
    int n = blockIdx.x;
    int t = threadIdx.x;
    int beg = g_off[n], end = g_off[n + 1];
    int d = end - beg;
    float s = 0.f, ss = 0.f;
    float mx = __int_as_float(0xff800000);
    float mn = __int_as_float(0x7f800000);
    __shared__ int ssrc[128];
    for (int base = beg; base < end; base += 128) {
        int cnt = min(128, end - base);
        if (t < cnt) ssrc[t] = g_csr[base + t];
        __syncthreads();
        #pragma unroll 4
        for (int i = 0; i < cnt; i++) {
            float m = h[(size_t)ssrc[i] * DH + t];
            s += m; ss += m * m;
            mx = fmaxf(mx, m); mn = fminf(mn, m);
        }
        __syncthreads();
    }
    float cntf = fmaxf((float)d, 1.f);
    float mean = s / cntf;
    float var = fmaxf(ss / cntf - mean * mean, 0.f);
    float stdv = sqrtf(var + 1e-5f);
    if (d == 0) { mx = 0.f; mn = 0.f; }

    __shared__ float sf[512];
    sf[t] = mean;
    sf[128 + t] = mx;
    sf[256 + t] = mn;
    sf[384 + t] = stdv;
    __syncthreads();

    size_t rowb = (size_t)n * KA2;
    #pragma unroll
    for (int p = t; p < KA2; p += 128) {
        unsigned hi, lo;
        split_pair(sf[2 * p], sf[2 * p + 1], hi, lo);
        g_Agh[rowb + p] = hi;
        g_Agl[rowb + p] = lo;
    }
}

// ---------------- factorized bf16x3 GEMM (ldmatrix fragments) ----------------
#define BMR 96
#define STG 19200       // u32 per stage: A 2*96*20 + B 6*128*20
#define SMEM_BYTES (2 * STG * 4)

__global__ __launch_bounds__(384, 1) void gemm_fact_kernel(
        const unsigned* __restrict__ Wimg, const float* __restrict__ bias,
        float* __restrict__ hout, int write_split) {
    extern __shared__ unsigned smem_u[];
    const uint32_t sb = smem_u32(smem_u);

    const int tid = threadIdx.x;
    const int lane = tid & 31;
    const int wid = tid >> 5;
    const int warp_m = wid >> 2;    // 0..2 (32 rows each)
    const int warp_n = wid & 3;     // 0..3 (32 cols each)
    const int lr = lane >> 2;       // 0..7
    const int lc = lane & 3;        // 0..3
    const int row0 = blockIdx.x * BMR;

    // ldmatrix per-lane geometry
    const int lg = lane >> 3;       // matrix id 0..3
    const int l8 = lane & 7;
    // A: mat0 rows+0 col+0 | mat1 rows+8 col+0 | mat2 rows+0 col+4 | mat3 rows+8 col+4
    const int a_row = ((lg & 1) << 3) + l8;
    const int a_col = (lg >> 1) << 2;
    // B: mat0 rows+0 col+0 | mat1 rows+0 col+4 | mat2 rows+8 col+0 | mat3 rows+8 col+4
    const int b_row = ((lg >> 1) << 3) + l8;
    const int b_col = (lg & 1) << 2;

    // per-lane u32-index bases (without stage/kb)
    const int a_base = (warp_m * 32 + a_row) * 20 + a_col;          // + mt*320 + kb
    const int b_base = 3840 + (warp_n * 32 + b_row) * 20 + b_col;   // + p*320 + w*5120 (+2560 lo) + kb

    float acc[3][2][4][4];
    #pragma unroll
    for (int g = 0; g < 3; g++)
        #pragma unroll
        for (int mt = 0; mt < 2; mt++)
            #pragma unroll
            for (int nt = 0; nt < 4; nt++)
                #pragma unroll
                for (int c = 0; c < 4; c++) acc[g][mt][nt][c] = 0.f;

    auto load_stage = [&](int j, int s) {
        uint32_t base = sb + s * (STG * 4);
        int nB = (j < 4) ? 1 : 3;
        int kt = (j < 4) ? j : j - 4;
        const unsigned* Ah = (j < 4) ? g_Hh : g_Agh;
        const unsigned* Al = (j < 4) ? g_Hl : g_Agl;
        int K2 = (j < 4) ? KH2 : KA2;
        const unsigned* Bsrc = Wimg + ((j < 4) ? (size_t)j * 4096
                                               : (size_t)16384 + (size_t)kt * 12288);
        int nch = 768 + nB * 1024;
        for (int c = tid; c < nch; c += 384) {
            uint32_t dst;
            const unsigned* src;
            if (c < 768) {
                int half = (c >= 384) ? 1 : 0;
                int rem = c - half * 384;
                int row = rem >> 2;
                int q = rem & 3;
                int node = row0 + row;
                if (node >= NN) node = NN - 1;
                src = (half ? Al : Ah) + (size_t)node * K2 + kt * 16 + q * 4;
                dst = base + (half * 1920 + row * 20 + q * 4) * 4;
            } else {
                int b = c - 768;
                int slot = b >> 9;
                int rem = b & 511;
                int r = rem >> 2;
                int q = rem & 3;
                src = Bsrc + slot * 2048 + r * 16 + q * 4;
                dst = base + (3840 + slot * 2560 + r * 20 + q * 4) * 4;
            }
            cp16(dst, src);
        }
        CP_COMMIT();
    };

    load_stage(0, 0);

    for (int j = 0; j < NJ; j++) {
        CP_WAIT0();
        __syncthreads();
        if (j + 1 < NJ) load_stage(j + 1, (j + 1) & 1);

        const uint32_t st = sb + (j & 1) * (STG * 4);
        int nB = (j < 4) ? 1 : 3;

        #pragma unroll
        for (int kb = 0; kb < 16; kb += 8) {
            unsigned ah[2][4], al[2][4];
            #pragma unroll
            for (int mt = 0; mt < 2; mt++) {
                uint32_t ad = st + (uint32_t)(a_base + mt * 320 + kb) * 4;
                ldsm4(ah[mt][0], ah[mt][1], ah[mt][2], ah[mt][3], ad);
                ldsm4(al[mt][0], al[mt][1], al[mt][2], al[mt][3], ad + 1920 * 4);
            }
            for (int w = 0; w < nB; w++) {
                int g = (j < 4) ? 0 : w;
                uint32_t bd = st + (uint32_t)(b_base + w * 5120 + kb) * 4;
                #pragma unroll
                for (int p = 0; p < 2; p++) {
                    unsigned bh[4], bl[4];
                    uint32_t bp = bd + (uint32_t)(p * 320) * 4;
                    ldsm4(bh[0], bh[1], bh[2], bh[3], bp);
                    ldsm4(bl[0], bl[1], bl[2], bl[3], bp + 2560 * 4);
                    #pragma unroll
                    for (int q = 0; q < 2; q++) {
                        int nt = 2 * p + q;
                        #pragma unroll
                        for (int mt = 0; mt < 2; mt++) {
                            mma_bf16(acc[g][mt][nt], ah[mt], &bh[2 * q]);
                            mma_bf16(acc[g][mt][nt], al[mt], &bh[2 * q]);
                            mma_bf16(acc[g][mt][nt], ah[mt], &bl[2 * q]);
                        }
                    }
                }
            }
        }
        __syncthreads();
    }

    // ---- epilogue ----
    float dlt = g_delta[0] * (1.f / (float)NN);
    float ampv[2][2], attv[2][2];
    #pragma unroll
    for (int mt = 0; mt < 2; mt++)
        #pragma unroll
        for (int rr = 0; rr < 2; rr++) {
            int row = row0 + warp_m * 32 + mt * 16 + lr + rr * 8;
            float a = 0.f, b = 0.f;
            if (row < NN) {
                float logd = logf((float)g_deg[row] + 1.f);
                a = logd / dlt;
                b = dlt / fmaxf(logd, 1e-5f);
            }
            ampv[mt][rr] = a;
            attv[mt][rr] = b;
        }

    #pragma unroll
    for (int mt = 0; mt < 2; mt++) {
        #pragma unroll
        for (int nt = 0; nt < 4; nt++) {
            int col = warp_n * 32 + nt * 8 + lc * 2;
            float b0 = bias[col], b1 = bias[col + 1];
            #pragma unroll
            for (int rr = 0; rr < 2; rr++) {
                int row = row0 + warp_m * 32 + mt * 16 + lr + rr * 8;
                if (row >= NN) continue;
                float amp = ampv[mt][rr], att = attv[mt][rr];
                int i0 = rr * 2;
                float2 v;
                v.x = fmaxf(acc[0][mt][nt][i0] + amp * acc[1][mt][nt][i0]
                            + att * acc[2][mt][nt][i0] + b0, 0.f);
                v.y = fmaxf(acc[0][mt][nt][i0 + 1] + amp * acc[1][mt][nt][i0 + 1]
                            + att * acc[2][mt][nt][i0 + 1] + b1, 0.f);
                *(float2*)&hout[(size_t)row * DH + col] = v;
                if (write_split) {
                    unsigned hi, lo;
                    split_pair(v.x, v.y, hi, lo);
                    g_Hh[(size_t)row * KH2 + (col >> 1)] = hi;
                    g_Hl[(size_t)row * KH2 + (col >> 1)] = lo;
                }
            }
        }
    }
}

// ---------------- pooling + bn/fc --------------------------------------------
#define POOL_NB 256
__global__ __launch_bounds__(128) void pool_kernel(
        const float* __restrict__ h, const int* __restrict__ batch) {
    int n0 = blockIdx.x * POOL_NB;
    int t = threadIdx.x;
    int nend = min(n0 + POOL_NB, NN);
    int cnt = nend - n0;
    __shared__ int sbm[POOL_NB];
    for (int i = t; i < cnt; i += 128) sbm[i] = batch[n0 + i];
    __syncthreads();
    float acc = 0.f;
    int cur = sbm[0];
    for (int i = 0; i < cnt; i++) {
        int b = sbm[i];
        if (b != cur) {
            atomicAdd(&g_pool[cur * DH + t], acc);
            acc = 0.f; cur = b;
        }
        acc += h[(size_t)(n0 + i) * DH + t];
    }
    atomicAdd(&g_pool[cur * DH + t], acc);
}

__global__ __launch_bounds__(128) void bnfc_kernel(
        const float* __restrict__ gamma, const float* __restrict__ beta,
        const float* __restrict__ fcW, const float* __restrict__ fcb,
        float* __restrict__ out) {
    __shared__ float sp[NG * DH];
    int t = threadIdx.x;
    for (int i = t; i < NG * DH; i += 128) sp[i] = g_pool[i];
    __syncthreads();
    float m = 0.f;
    #pragma unroll 4
    for (int g = 0; g < NG; g++) m += sp[g * DH + t];
    m *= (1.f / NG);
    float v = 0.f;
    #pragma unroll 4
    for (int g = 0; g < NG; g++) { float d = sp[g * DH + t] - m; v += d * d; }
    v *= (1.f / NG);
    float rs = rsqrtf(v + 1e-5f);
    float ga = gamma[t], be = beta[t];
    for (int g = 0; g < NG; g++)
        sp[g * DH + t] = (sp[g * DH + t] - m) * rs * ga + be;
    __syncthreads();
    for (int i = t; i < NG * DLAT; i += 128) {
        int g = i / DLAT, j = i % DLAT;
        float s = fcb[j];
        #pragma unroll 8
        for (int c = 0; c < DH; c++) s += sp[g * DH + c] * fcW[c * DLAT + j];
        out[i] = s;
    }
}

// ---------------- launch ------------------------------------------------------
extern "C" void kernel_launch(void* const* d_in, const int* in_sizes, int n_in,
                              void* d_out, int out_size) {
    const float* x     = (const float*)d_in[0];
    const int*   ei    = (const int*)d_in[1];
    const int*   batch = (const int*)d_in[2];
    const float* W0 = (const float*)d_in[3];  const float* b0 = (const float*)d_in[4];
    const float* W1 = (const float*)d_in[5];  const float* b1 = (const float*)d_in[6];
    const float* W2 = (const float*)d_in[7];  const float* b2 = (const float*)d_in[8];
    const float* gamma = (const float*)d_in[9];
    const float* beta  = (const float*)d_in[10];
    const float* fcW   = (const float*)d_in[11];
    const float* fcb   = (const float*)d_in[12];
    float* out = (float*)d_out;

    void *p_deg, *p_cur, *p_delta, *p_pool, *p_h0, *p_h1, *p_w;
    cudaGetSymbolAddress(&p_deg,   g_deg);
    cudaGetSymbolAddress(&p_cur,   g_cur);
    cudaGetSymbolAddress(&p_delta, g_delta);
    cudaGetSymbolAddress(&p_pool,  g_pool);
    cudaGetSymbolAddress(&p_h0,    g_h0);
    cudaGetSymbolAddress(&p_h1,    g_h1);
    cudaGetSymbolAddress(&p_w,     g_W);
    float* h0 = (float*)p_h0;
    float* h1 = (float*)p_h1;
    unsigned* wimg = (unsigned*)p_w;

    cudaFuncSetAttribute(gemm_fact_kernel,
                         cudaFuncAttributeMaxDynamicSharedMemorySize, SMEM_BYTES);

    cudaMemsetAsync(p_deg,   0, NN * sizeof(int));
    cudaMemsetAsync(p_cur,   0, NN * sizeof(int));
    cudaMemsetAsync(p_delta, 0, sizeof(float));
    cudaMemsetAsync(p_pool,  0, NG * DH * sizeof(float));

    int wthreads = 832 * 128;
    int wblocks = (wthreads + 255) / 256;
    wsplit_kernel<<<wblocks, 256>>>(W0, wimg);
    wsplit_kernel<<<wblocks, 256>>>(W1, wimg + WLAYER);
    wsplit_kernel<<<wblocks, 256>>>(W2, wimg + 2 * WLAYER);
    xsplit_kernel<<<(NN * KH2 + 255) / 256, 256>>>(x);

    int eblocks = (NE + 1023) / 1024;
    hist_kernel<<<eblocks, 1024>>>(ei);
    scan_kernel<<<1, 1024>>>();
    scatter_kernel<<<eblocks, 1024>>>(ei);
    delta_kernel<<<128, 256>>>();

    int gblocks = (NN + BMR - 1) / BMR;   // 521

    agg_kernel<<<NN, 128>>>(x);
    gemm_fact_kernel<<<gblocks, 384, SMEM_BYTES>>>(wimg, b0, h0, 1);
    agg_kernel<<<NN, 128>>>(h0);
    gemm_fact_kernel<<<gblocks, 384, SMEM_BYTES>>>(wimg + WLAYER, b1, h1, 1);
    agg_kernel<<<NN, 128>>>(h1);
    gemm_fact_kernel<<<gblocks, 384, SMEM_BYTES>>>(wimg + 2 * WLAYER, b2, h0, 0);

    pool_kernel<<<(NN + POOL_NB - 1) / POOL_NB, 128>>>(h0, batch);
    bnfc_kernel<<<1, 128>>>(gamma, beta, fcW, fcb, out);
}